// round 5
// baseline (speedup 1.0000x reference)
#include <cuda_runtime.h>
#include <math.h>

// GPT-2 small config (fixed by the problem)
#define NB   2
#define NT   1024
#define ND   768
#define NH   12
#define NL   12
#define NV   50257
#define NHD  64
#define NTOK (NB * NT)        // 2048 token rows
#define N3D  (3 * ND)         // 2304
#define N4D  (4 * ND)         // 3072

// ---------------------------------------------------------------------------
// Scratch (device globals; allocation inside kernel_launch is forbidden)
// ---------------------------------------------------------------------------
__device__ float g_x  [NTOK * ND];          // residual stream
__device__ float g_h  [NTOK * ND];          // layernorm output
__device__ float g_qkv[NTOK * N3D];         // qkv projections
__device__ float g_ao [NTOK * ND];          // attention output (pre-proj)
__device__ float g_fc1[NTOK * N4D];         // MLP hidden
__device__ float g_att[(size_t)NB * NH * NT * NT];  // attention matrix (~100MB)

// ---------------------------------------------------------------------------
// Embedding: x = wte[idx] + pos
// ---------------------------------------------------------------------------
__global__ __launch_bounds__(256) void embed_k(const int* __restrict__ idx,
                                               const float* __restrict__ wte,
                                               const float* __restrict__ pos) {
    int i = blockIdx.x * 256 + threadIdx.x;
    if (i >= NTOK * ND) return;
    int tok = i / ND;
    int d   = i - tok * ND;
    int t   = tok & (NT - 1);
    g_x[i] = wte[(size_t)idx[tok] * ND + d] + pos[t * ND + d];
}

// ---------------------------------------------------------------------------
// LayerNorm: one block per token row (D=768, 256 threads x 3 elems)
// ---------------------------------------------------------------------------
__global__ __launch_bounds__(256) void ln_k(const float* __restrict__ in,
                                            const float* __restrict__ gamma,
                                            const float* __restrict__ beta,
                                            float* __restrict__ out) {
    int row = blockIdx.x;
    int tid = threadIdx.x;
    const float* x = in + (size_t)row * ND;
    float v0 = x[tid], v1 = x[tid + 256], v2 = x[tid + 512];

    __shared__ float red[256];
    __shared__ float s_mean, s_inv;

    red[tid] = v0 + v1 + v2;
    __syncthreads();
    for (int off = 128; off > 0; off >>= 1) {
        if (tid < off) red[tid] += red[tid + off];
        __syncthreads();
    }
    if (tid == 0) s_mean = red[0] * (1.0f / ND);
    __syncthreads();
    float m  = s_mean;
    float d0 = v0 - m, d1 = v1 - m, d2 = v2 - m;

    red[tid] = d0 * d0 + d1 * d1 + d2 * d2;
    __syncthreads();
    for (int off = 128; off > 0; off >>= 1) {
        if (tid < off) red[tid] += red[tid + off];
        __syncthreads();
    }
    if (tid == 0) s_inv = rsqrtf(red[0] * (1.0f / ND) + 1e-5f);
    __syncthreads();
    float inv = s_inv;

    float* o = out + (size_t)row * ND;
    o[tid]       = d0 * inv * gamma[tid]       + beta[tid];
    o[tid + 256] = d1 * inv * gamma[tid + 256] + beta[tid + 256];
    o[tid + 512] = d2 * inv * gamma[tid + 512] + beta[tid + 512];
}

// ---------------------------------------------------------------------------
// SGEMM: C[M,N] = A[M,K] @ W + epilogue
//   TB=false: W is [K,N] row-major.  TB=true: W is [N,K] row-major (B^T).
//   EPI: 0 = +bias, 1 = +bias+residual, 2 = +bias then exact GELU, 3 = none
// 128x128 block tile, BK=16, 256 threads, 8x8 per thread.
// ---------------------------------------------------------------------------
__device__ __forceinline__ float gelu_f(float v) {
    return 0.5f * v * (1.0f + erff(v * 0.70710678118654752f));
}

template <bool TB, int EPI>
__global__ __launch_bounds__(256) void sgemm_k(const float* __restrict__ A,
                                               const float* __restrict__ W,
                                               const float* __restrict__ bias,
                                               const float* __restrict__ res,
                                               float* __restrict__ C,
                                               int M, int N, int K) {
    __shared__ __align__(16) float As[16][132];  // padded: kills STS conflicts
    __shared__ __align__(16) float Bs[16][132];

    const int bm  = blockIdx.y * 128;
    const int bn  = blockIdx.x * 128;
    const int tid = threadIdx.x;
    const int tx  = tid & 15;   // 16 cols of threads
    const int ty  = tid >> 4;   // 16 rows of threads

    float acc[8][8];
#pragma unroll
    for (int i = 0; i < 8; i++)
#pragma unroll
        for (int j = 0; j < 8; j++) acc[i][j] = 0.0f;

    for (int k0 = 0; k0 < K; k0 += 16) {
        // A tile 128x16 (2048 elems / 256 threads = 8 each)
#pragma unroll
        for (int i = 0; i < 8; i++) {
            int idx = tid + i * 256;
            int m   = idx >> 4;
            int kk  = idx & 15;
            int gm  = bm + m;
            float v = (gm < M) ? A[(size_t)gm * K + k0 + kk] : 0.0f;
            As[kk][m] = v;
        }
        // B tile 16x128
#pragma unroll
        for (int i = 0; i < 8; i++) {
            int idx = tid + i * 256;
            int kk  = idx >> 7;
            int n   = idx & 127;
            int gn  = bn + n;
            float v = 0.0f;
            if (gn < N) {
                if (TB) v = W[(size_t)gn * K + (k0 + kk)];
                else    v = W[(size_t)(k0 + kk) * N + gn];
            }
            Bs[kk][n] = v;
        }
        __syncthreads();

#pragma unroll
        for (int kk = 0; kk < 16; kk++) {
            float a[8], b[8];
            *(float4*)&a[0] = *(const float4*)&As[kk][ty * 8];
            *(float4*)&a[4] = *(const float4*)&As[kk][ty * 8 + 4];
            *(float4*)&b[0] = *(const float4*)&Bs[kk][tx * 8];
            *(float4*)&b[4] = *(const float4*)&Bs[kk][tx * 8 + 4];
#pragma unroll
            for (int i = 0; i < 8; i++)
#pragma unroll
                for (int j = 0; j < 8; j++)
                    acc[i][j] = fmaf(a[i], b[j], acc[i][j]);
        }
        __syncthreads();
    }

#pragma unroll
    for (int i = 0; i < 8; i++) {
        int gm = bm + ty * 8 + i;
        if (gm >= M) continue;
#pragma unroll
        for (int j = 0; j < 8; j++) {
            int gn = bn + tx * 8 + j;
            if (gn >= N) continue;
            float v = acc[i][j];
            if (EPI != 3) v += bias[gn];
            if (EPI == 1) v += res[(size_t)gm * N + gn];
            if (EPI == 2) v = gelu_f(v);
            C[(size_t)gm * N + gn] = v;
        }
    }
}

// ---------------------------------------------------------------------------
// Attention scores: S[bh, q, k] = (Q . K) * 1/8   (64x64 tiles over 64 dims)
// Tiles fully above the diagonal are skipped; masking done in softmax.
// ---------------------------------------------------------------------------
__global__ __launch_bounds__(256) void attn_scores_k() {
    int bh = blockIdx.z;
    int b  = bh / NH;
    int h  = bh - b * NH;
    int q0 = blockIdx.y * 64;
    int k0 = blockIdx.x * 64;
    if (k0 > q0) return;  // whole tile masked

    __shared__ float Qs[64][65];
    __shared__ float Ks[64][65];
    const float* base = g_qkv + (size_t)b * NT * N3D + h * NHD;

    for (int i = threadIdx.x; i < 64 * 64; i += 256) {
        int r = i >> 6, c = i & 63;
        Qs[r][c] = base[(size_t)(q0 + r) * N3D + c];         // Q slice
        Ks[r][c] = base[(size_t)(k0 + r) * N3D + ND + c];    // K slice
    }
    __syncthreads();

    int tx = threadIdx.x & 15, ty = threadIdx.x >> 4;
    float acc[4][4] = {};
#pragma unroll
    for (int d = 0; d < 64; d++) {
        float a[4], bb[4];
#pragma unroll
        for (int i = 0; i < 4; i++) a[i] = Qs[ty * 4 + i][d];
#pragma unroll
        for (int j = 0; j < 4; j++) bb[j] = Ks[tx * 4 + j][d];
#pragma unroll
        for (int i = 0; i < 4; i++)
#pragma unroll
            for (int j = 0; j < 4; j++)
                acc[i][j] = fmaf(a[i], bb[j], acc[i][j]);
    }

    float* S = g_att + ((size_t)bh * NT + q0) * NT + k0;
#pragma unroll
    for (int i = 0; i < 4; i++)
#pragma unroll
        for (int j = 0; j < 4; j++)
            S[(size_t)(ty * 4 + i) * NT + tx * 4 + j] = acc[i][j] * 0.125f;
}

// ---------------------------------------------------------------------------
// Causal softmax over each row; masked (k > q) entries written as exactly 0.
// ---------------------------------------------------------------------------
__global__ __launch_bounds__(256) void attn_softmax_k() {
    int row = blockIdx.x;            // bh*NT + q
    int tid = threadIdx.x;
    int q   = row & (NT - 1);
    float* S = g_att + (size_t)row * NT;

    __shared__ float red[256];

    float mx = -1e30f;
    for (int k = tid; k <= q; k += 256) mx = fmaxf(mx, S[k]);
    red[tid] = mx;
    __syncthreads();
    for (int off = 128; off > 0; off >>= 1) {
        if (tid < off) red[tid] = fmaxf(red[tid], red[tid + off]);
        __syncthreads();
    }
    mx = red[0];
    __syncthreads();

    float sum = 0.0f;
    for (int k = tid; k <= q; k += 256) {
        float e = __expf(S[k] - mx);
        S[k] = e;
        sum += e;
    }
    red[tid] = sum;
    __syncthreads();
    for (int off = 128; off > 0; off >>= 1) {
        if (tid < off) red[tid] += red[tid + off];
        __syncthreads();
    }
    float inv = 1.0f / red[0];

    for (int k = tid; k < NT; k += 256)
        S[k] = (k <= q) ? S[k] * inv : 0.0f;
}

// ---------------------------------------------------------------------------
// O = P @ V  (64 q-rows per block, full 64-dim output, k-loop stops at diag)
// ---------------------------------------------------------------------------
__global__ __launch_bounds__(256) void attn_av_k() {
    int bh = blockIdx.y;
    int b  = bh / NH;
    int h  = bh - b * NH;
    int q0 = blockIdx.x * 64;

    __shared__ float Ps[64][65];
    __shared__ float Vs[64][65];
    const float* P     = g_att + ((size_t)bh * NT + q0) * NT;
    const float* vbase = g_qkv + (size_t)b * NT * N3D + 2 * ND + h * NHD;

    int tx = threadIdx.x & 15, ty = threadIdx.x >> 4;
    float acc[4][4] = {};

    for (int k0 = 0; k0 <= q0; k0 += 64) {
        for (int i = threadIdx.x; i < 64 * 64; i += 256) {
            int r = i >> 6, c = i & 63;
            Ps[r][c] = P[(size_t)r * NT + k0 + c];
            Vs[r][c] = vbase[(size_t)(k0 + r) * N3D + c];
        }
        __syncthreads();
#pragma unroll
        for (int kk = 0; kk < 64; kk++) {
            float a[4], bb[4];
#pragma unroll
            for (int i = 0; i < 4; i++) a[i] = Ps[ty * 4 + i][kk];
#pragma unroll
            for (int j = 0; j < 4; j++) bb[j] = Vs[kk][tx * 4 + j];
#pragma unroll
            for (int i = 0; i < 4; i++)
#pragma unroll
                for (int j = 0; j < 4; j++)
                    acc[i][j] = fmaf(a[i], bb[j], acc[i][j]);
        }
        __syncthreads();
    }

    // scatter back to [B,T,D] layout
    float* o = g_ao + ((size_t)b * NT + q0) * ND + h * NHD;
#pragma unroll
    for (int i = 0; i < 4; i++)
#pragma unroll
        for (int j = 0; j < 4; j++)
            o[(size_t)(ty * 4 + i) * ND + tx * 4 + j] = acc[i][j];
}

// ---------------------------------------------------------------------------
// Host driver — graph-capturable: kernel launches only.
// ---------------------------------------------------------------------------
extern "C" void kernel_launch(void* const* d_in, const int* in_sizes, int n_in,
                              void* d_out, int out_size) {
    const int*   idx   = (const int*)  d_in[0];
    const float* wte   = (const float*)d_in[1];
    const float* pos   = (const float*)d_in[2];
    const float* ln1g  = (const float*)d_in[3];
    const float* ln1b  = (const float*)d_in[4];
    const float* qkvw  = (const float*)d_in[5];
    const float* qkvb  = (const float*)d_in[6];
    const float* projw = (const float*)d_in[7];
    const float* projb = (const float*)d_in[8];
    const float* ln2g  = (const float*)d_in[9];
    const float* ln2b  = (const float*)d_in[10];
    const float* fc1w  = (const float*)d_in[11];
    const float* fc1b  = (const float*)d_in[12];
    const float* fc2w  = (const float*)d_in[13];
    const float* fc2b  = (const float*)d_in[14];
    const float* lnfg  = (const float*)d_in[15];
    const float* lnfb  = (const float*)d_in[16];

    float *px, *ph, *pao, *pfc1;
    cudaGetSymbolAddress((void**)&px,   g_x);
    cudaGetSymbolAddress((void**)&ph,   g_h);
    cudaGetSymbolAddress((void**)&pao,  g_ao);
    cudaGetSymbolAddress((void**)&pfc1, g_fc1);
    float* pqkv;
    cudaGetSymbolAddress((void**)&pqkv, g_qkv);

    embed_k<<<(NTOK * ND + 255) / 256, 256>>>(idx, wte, pos);

    for (int l = 0; l < NL; l++) {
        // --- attention half ---
        ln_k<<<NTOK, 256>>>(px, ln1g + (size_t)l * ND, ln1b + (size_t)l * ND, ph);

        dim3 gq(N3D / 128, NTOK / 128);
        sgemm_k<false, 0><<<gq, 256>>>(ph, qkvw + (size_t)l * ND * N3D,
                                       qkvb + (size_t)l * N3D, nullptr,
                                       pqkv, NTOK, N3D, ND);

        dim3 gs(NT / 64, NT / 64, NB * NH);
        attn_scores_k<<<gs, 256>>>();
        attn_softmax_k<<<NB * NH * NT, 256>>>();
        dim3 ga(NT / 64, NB * NH);
        attn_av_k<<<ga, 256>>>();

        dim3 gp(ND / 128, NTOK / 128);
        sgemm_k<false, 1><<<gp, 256>>>(pao, projw + (size_t)l * ND * ND,
                                       projb + (size_t)l * ND, px,
                                       px, NTOK, ND, ND);

        // --- MLP half ---
        ln_k<<<NTOK, 256>>>(px, ln2g + (size_t)l * ND, ln2b + (size_t)l * ND, ph);

        dim3 g1(N4D / 128, NTOK / 128);
        sgemm_k<false, 2><<<g1, 256>>>(ph, fc1w + (size_t)l * ND * N4D,
                                       fc1b + (size_t)l * N4D, nullptr,
                                       pfc1, NTOK, N4D, ND);

        dim3 g2(ND / 128, NTOK / 128);
        sgemm_k<false, 1><<<g2, 256>>>(pfc1, fc2w + (size_t)l * N4D * ND,
                                       fc2b + (size_t)l * ND, px,
                                       px, NTOK, ND, N4D);
    }

    // final LN + tied head (W = wte is [V, D] row-major -> trans-B GEMM)
    ln_k<<<NTOK, 256>>>(px, lnfg, lnfb, ph);
    dim3 gh((NV + 127) / 128, NTOK / 128);
    sgemm_k<true, 3><<<gh, 256>>>(ph, wte, nullptr, nullptr,
                                  (float*)d_out, NTOK, NV, ND);
}

// round 7
// speedup vs baseline: 3.5804x; 3.5804x over previous
#include <cuda_runtime.h>
#include <math.h>
#include <stdint.h>

// GPT-2 small config (fixed by the problem)
#define NB   2
#define NT   1024
#define ND   768
#define NH   12
#define NL   12
#define NV   50257
#define NVP  50304                // NV padded to multiple of 128
#define NHD  64
#define NTOK (NB * NT)            // 2048 token rows
#define N3D  (3 * ND)             // 2304
#define N4D  (4 * ND)             // 3072

// ---------------------------------------------------------------------------
// Scratch (device globals; allocation inside kernel_launch is forbidden)
// ---------------------------------------------------------------------------
__device__ float g_x  [NTOK * ND];
__device__ float g_h  [NTOK * ND];          // LN out (tf32-rounded)
__device__ float g_qkv[NTOK * N3D];
__device__ float g_ao [NTOK * ND];          // attn out (tf32-rounded)
__device__ float g_fc1[NTOK * N4D];         // GELU out (tf32-rounded)
__device__ float g_att[(size_t)NB * NH * NT * NT];      // ~100MB

// tf32 weights, transposed to [N,K] so GEMM B-operand is K-major like A
__device__ float g_wteT [(size_t)NVP * ND];             // rows >= NV zeroed
__device__ float g_qkvT [(size_t)NL * N3D * ND];
__device__ float g_projT[(size_t)NL * ND * ND];
__device__ float g_fc1T [(size_t)NL * N4D * ND];
__device__ float g_fc2T [(size_t)NL * ND * N4D];

// ---------------------------------------------------------------------------
// Helpers
// ---------------------------------------------------------------------------
__device__ __forceinline__ uint32_t smem_u32(const void* p) {
    uint32_t a;
    asm("{ .reg .u64 t; cvta.to.shared.u64 t, %1; cvt.u32.u64 %0, t; }"
        : "=r"(a) : "l"(p));
    return a;
}
__device__ __forceinline__ float tf32r(float x) {   // round-to-nearest tf32
    uint32_t r;
    asm("cvt.rna.tf32.f32 %0, %1;" : "=r"(r) : "f"(x));
    return __uint_as_float(r);
}
__device__ __forceinline__ void cp16(uint32_t dst, const void* src) {
    asm volatile("cp.async.cg.shared.global [%0], [%1], 16;"
                 :: "r"(dst), "l"(src) : "memory");
}
__device__ __forceinline__ void mma_tf32(float* c, const uint32_t* a,
                                         const uint32_t* b) {
    asm volatile(
        "mma.sync.aligned.m16n8k8.row.col.f32.tf32.tf32.f32 "
        "{%0,%1,%2,%3}, {%4,%5,%6,%7}, {%8,%9}, {%0,%1,%2,%3};"
        : "+f"(c[0]), "+f"(c[1]), "+f"(c[2]), "+f"(c[3])
        : "r"(a[0]), "r"(a[1]), "r"(a[2]), "r"(a[3]), "r"(b[0]), "r"(b[1]));
}
__device__ __forceinline__ float gelu_f(float v) {
    return 0.5f * v * (1.0f + erff(v * 0.70710678118654752f));
}

// smem: two stages, each stage = A tile + B tile, tile = 128 rows x 144B pitch
#define TILE_B   (128 * 144)
#define SA_ST(s) ((s) * 2 * TILE_B)
#define SB_ST(s) ((s) * 2 * TILE_B + TILE_B)
#define SMEM_GEMM (4 * TILE_B)      // 73728 B

// ---------------------------------------------------------------------------
// tf32 mma.sync GEMM: C[M,N] = A[M,K] @ W  (Bt = W^T as [N,K], rows padded)
//   A must already be tf32-rounded. EPI: 0 +bias, 1 +bias+res, 2 +bias+GELU
//   (output re-rounded to tf32), 3 none.
// Grid (ceil(N/128), M/128), 256 threads. K%32==0, K/32>=2, M%128==0.
// ---------------------------------------------------------------------------
template <int EPI>
__global__ __launch_bounds__(256, 2) void tc_gemm_k(
    const float* __restrict__ A, const float* __restrict__ Bt,
    const float* __restrict__ bias, const float* __restrict__ res,
    float* __restrict__ C, int N, int K)
{
    extern __shared__ char smem[];
    const uint32_t sb = smem_u32(smem);
    const int tid  = threadIdx.x;
    const int lane = tid & 31;
    const int wid  = tid >> 5;
    const int wm   = (wid >> 2) * 64;   // warp m-offset (2 rows of warps)
    const int wn   = (wid & 3) * 32;    // warp n-offset (4 cols of warps)
    const int bm   = blockIdx.y * 128;
    const int bn   = blockIdx.x * 128;
    const int g    = lane >> 2;         // 0..7
    const int t    = lane & 3;          // 0..3
    const int T    = K >> 5;            // BK=32 steps

    auto load_stage = [&](int step, int s) {
        const float* Ap = A  + (size_t)bm * K + step * 32;
        const float* Bp = Bt + (size_t)bn * K + step * 32;
#pragma unroll
        for (int i = 0; i < 4; i++) {
            int f = tid + i * 256;      // 1024 16B-chunks per operand
            int r = f >> 3, c = f & 7;
            cp16(sb + SA_ST(s) + r * 144 + c * 16, Ap + (size_t)r * K + c * 4);
            cp16(sb + SB_ST(s) + r * 144 + c * 16, Bp + (size_t)r * K + c * 4);
        }
        asm volatile("cp.async.commit_group;" ::: "memory");
    };

    float acc[4][4][4];                 // [mi][ni][frag]
#pragma unroll
    for (int i = 0; i < 4; i++)
#pragma unroll
        for (int j = 0; j < 4; j++)
#pragma unroll
            for (int r = 0; r < 4; r++) acc[i][j][r] = 0.0f;

    load_stage(0, 0);
    load_stage(1, 1);

    for (int ts = 0; ts < T; ts++) {
        const int s = ts & 1;
        if (ts + 1 < T) asm volatile("cp.async.wait_group 1;" ::: "memory");
        else            asm volatile("cp.async.wait_group 0;" ::: "memory");
        __syncthreads();

        const float* sa = (const float*)(smem + SA_ST(s));
        const float* sbb = (const float*)(smem + SB_ST(s));
#pragma unroll
        for (int kk = 0; kk < 4; kk++) {
            const int col = kk * 8 + t;
            uint32_t af[4][4], bf[4][2];
#pragma unroll
            for (int mi = 0; mi < 4; mi++) {
                const float* b0 = sa + (wm + mi * 16) * 36;
                af[mi][0] = __float_as_uint(b0[(g)     * 36 + col]);
                af[mi][1] = __float_as_uint(b0[(g + 8) * 36 + col]);
                af[mi][2] = __float_as_uint(b0[(g)     * 36 + col + 4]);
                af[mi][3] = __float_as_uint(b0[(g + 8) * 36 + col + 4]);
            }
#pragma unroll
            for (int ni = 0; ni < 4; ni++) {
                const float* b0 = sbb + (wn + ni * 8) * 36;
                bf[ni][0] = __float_as_uint(b0[g * 36 + col]);
                bf[ni][1] = __float_as_uint(b0[g * 36 + col + 4]);
            }
#pragma unroll
            for (int mi = 0; mi < 4; mi++)
#pragma unroll
                for (int ni = 0; ni < 4; ni++)
                    mma_tf32(acc[mi][ni], af[mi], bf[ni]);
        }
        __syncthreads();
        if (ts + 2 < T) load_stage(ts + 2, s);
    }

    // Epilogue: fragment-direct stores (8-float contiguous per 4-lane group)
#pragma unroll
    for (int mi = 0; mi < 4; mi++) {
#pragma unroll
        for (int ni = 0; ni < 4; ni++) {
            const int gn = bn + wn + ni * 8 + t * 2;
#pragma unroll
            for (int r = 0; r < 2; r++) {
                const int gm = bm + wm + mi * 16 + g + r * 8;
                float v0 = acc[mi][ni][r * 2 + 0];
                float v1 = acc[mi][ni][r * 2 + 1];
                if (EPI != 3) {
                    v0 += bias[gn];
                    v1 += bias[gn + 1];
                }
                if (EPI == 1) {
                    v0 += res[(size_t)gm * N + gn];
                    v1 += res[(size_t)gm * N + gn + 1];
                }
                if (EPI == 2) {
                    v0 = tf32r(gelu_f(v0));
                    v1 = tf32r(gelu_f(v1));
                }
                if (gn < N)     C[(size_t)gm * N + gn]     = v0;
                if (gn + 1 < N) C[(size_t)gm * N + gn + 1] = v1;
            }
        }
    }
}

// ---------------------------------------------------------------------------
// Weight prep: transpose [K,N] -> [N,K] with tf32 rounding (layer via z)
// ---------------------------------------------------------------------------
__global__ __launch_bounds__(256) void transpose_cvt_k(
    const float* __restrict__ in, float* __restrict__ out,
    int Kd, int Nd, size_t in_ls, size_t out_ls)
{
    __shared__ float t[32][33];
    const float* ip = in  + blockIdx.z * in_ls;
    float*       op = out + blockIdx.z * out_ls;
    int n0 = blockIdx.x * 32, k0 = blockIdx.y * 32;
    int tx = threadIdx.x & 31, ty = threadIdx.x >> 5;   // 32 x 8
#pragma unroll
    for (int i = 0; i < 32; i += 8)
        t[ty + i][tx] = ip[(size_t)(k0 + ty + i) * Nd + n0 + tx];
    __syncthreads();
#pragma unroll
    for (int i = 0; i < 32; i += 8)
        op[(size_t)(n0 + ty + i) * Kd + k0 + tx] = tf32r(t[tx][ty + i]);
}

__global__ __launch_bounds__(256) void wte_cvt_k(const float* __restrict__ wte) {
    size_t i = (size_t)blockIdx.x * 256 + threadIdx.x;
    if (i >= (size_t)NVP * ND) return;
    int n = (int)(i / ND);
    g_wteT[i] = (n < NV) ? tf32r(wte[i]) : 0.0f;
}

// ---------------------------------------------------------------------------
// Embedding
// ---------------------------------------------------------------------------
__global__ __launch_bounds__(256) void embed_k(const int* __restrict__ idx,
                                               const float* __restrict__ wte,
                                               const float* __restrict__ pos) {
    int i = blockIdx.x * 256 + threadIdx.x;
    if (i >= NTOK * ND) return;
    int tok = i / ND;
    int d   = i - tok * ND;
    int t   = tok & (NT - 1);
    g_x[i] = wte[(size_t)idx[tok] * ND + d] + pos[t * ND + d];
}

// ---------------------------------------------------------------------------
// LayerNorm: one block per token row; output tf32-rounded (feeds mma GEMMs)
// ---------------------------------------------------------------------------
__global__ __launch_bounds__(256) void ln_k(const float* __restrict__ in,
                                            const float* __restrict__ gamma,
                                            const float* __restrict__ beta,
                                            float* __restrict__ out) {
    int row = blockIdx.x;
    int tid = threadIdx.x;
    const float* x = in + (size_t)row * ND;
    float v0 = x[tid], v1 = x[tid + 256], v2 = x[tid + 512];

    __shared__ float red[256];
    __shared__ float s_mean, s_inv;

    red[tid] = v0 + v1 + v2;
    __syncthreads();
    for (int off = 128; off > 0; off >>= 1) {
        if (tid < off) red[tid] += red[tid + off];
        __syncthreads();
    }
    if (tid == 0) s_mean = red[0] * (1.0f / ND);
    __syncthreads();
    float m  = s_mean;
    float d0 = v0 - m, d1 = v1 - m, d2 = v2 - m;

    red[tid] = d0 * d0 + d1 * d1 + d2 * d2;
    __syncthreads();
    for (int off = 128; off > 0; off >>= 1) {
        if (tid < off) red[tid] += red[tid + off];
        __syncthreads();
    }
    if (tid == 0) s_inv = rsqrtf(red[0] * (1.0f / ND) + 1e-5f);
    __syncthreads();
    float inv = s_inv;

    float* o = out + (size_t)row * ND;
    o[tid]       = tf32r(d0 * inv * gamma[tid]       + beta[tid]);
    o[tid + 256] = tf32r(d1 * inv * gamma[tid + 256] + beta[tid + 256]);
    o[tid + 512] = tf32r(d2 * inv * gamma[tid + 512] + beta[tid + 512]);
}

// ---------------------------------------------------------------------------
// Attention (SIMT; next round's target)
// ---------------------------------------------------------------------------
__global__ __launch_bounds__(256) void attn_scores_k() {
    int bh = blockIdx.z;
    int b  = bh / NH;
    int h  = bh - b * NH;
    int q0 = blockIdx.y * 64;
    int k0 = blockIdx.x * 64;
    if (k0 > q0) return;

    __shared__ float Qs[64][65];
    __shared__ float Ks[64][65];
    const float* base = g_qkv + (size_t)b * NT * N3D + h * NHD;

    for (int i = threadIdx.x; i < 64 * 64; i += 256) {
        int r = i >> 6, c = i & 63;
        Qs[r][c] = base[(size_t)(q0 + r) * N3D + c];
        Ks[r][c] = base[(size_t)(k0 + r) * N3D + ND + c];
    }
    __syncthreads();

    int tx = threadIdx.x & 15, ty = threadIdx.x >> 4;
    float acc[4][4] = {};
#pragma unroll
    for (int d = 0; d < 64; d++) {
        float a[4], bb[4];
#pragma unroll
        for (int i = 0; i < 4; i++) a[i] = Qs[ty * 4 + i][d];
#pragma unroll
        for (int j = 0; j < 4; j++) bb[j] = Ks[tx * 4 + j][d];
#pragma unroll
        for (int i = 0; i < 4; i++)
#pragma unroll
            for (int j = 0; j < 4; j++)
                acc[i][j] = fmaf(a[i], bb[j], acc[i][j]);
    }

    float* S = g_att + ((size_t)bh * NT + q0) * NT + k0;
#pragma unroll
    for (int i = 0; i < 4; i++)
#pragma unroll
        for (int j = 0; j < 4; j++)
            S[(size_t)(ty * 4 + i) * NT + tx * 4 + j] = acc[i][j] * 0.125f;
}

__global__ __launch_bounds__(256) void attn_softmax_k() {
    int row = blockIdx.x;
    int tid = threadIdx.x;
    int q   = row & (NT - 1);
    float* S = g_att + (size_t)row * NT;

    __shared__ float red[256];

    float mx = -1e30f;
    for (int k = tid; k <= q; k += 256) mx = fmaxf(mx, S[k]);
    red[tid] = mx;
    __syncthreads();
    for (int off = 128; off > 0; off >>= 1) {
        if (tid < off) red[tid] = fmaxf(red[tid], red[tid + off]);
        __syncthreads();
    }
    mx = red[0];
    __syncthreads();

    float sum = 0.0f;
    for (int k = tid; k <= q; k += 256) {
        float e = __expf(S[k] - mx);
        S[k] = e;
        sum += e;
    }
    red[tid] = sum;
    __syncthreads();
    for (int off = 128; off > 0; off >>= 1) {
        if (tid < off) red[tid] += red[tid + off];
        __syncthreads();
    }
    float inv = 1.0f / red[0];

    for (int k = tid; k < NT; k += 256)
        S[k] = (k <= q) ? S[k] * inv : 0.0f;
}

__global__ __launch_bounds__(256) void attn_av_k() {
    int bh = blockIdx.y;
    int b  = bh / NH;
    int h  = bh - b * NH;
    int q0 = blockIdx.x * 64;

    __shared__ float Ps[64][65];
    __shared__ float Vs[64][65];
    const float* P     = g_att + ((size_t)bh * NT + q0) * NT;
    const float* vbase = g_qkv + (size_t)b * NT * N3D + 2 * ND + h * NHD;

    int tx = threadIdx.x & 15, ty = threadIdx.x >> 4;
    float acc[4][4] = {};

    for (int k0 = 0; k0 <= q0; k0 += 64) {
        for (int i = threadIdx.x; i < 64 * 64; i += 256) {
            int r = i >> 6, c = i & 63;
            Ps[r][c] = P[(size_t)r * NT + k0 + c];
            Vs[r][c] = vbase[(size_t)(k0 + r) * N3D + c];
        }
        __syncthreads();
#pragma unroll
        for (int kk = 0; kk < 64; kk++) {
            float a[4], bb[4];
#pragma unroll
            for (int i = 0; i < 4; i++) a[i] = Ps[ty * 4 + i][kk];
#pragma unroll
            for (int j = 0; j < 4; j++) bb[j] = Vs[kk][tx * 4 + j];
#pragma unroll
            for (int i = 0; i < 4; i++)
#pragma unroll
                for (int j = 0; j < 4; j++)
                    acc[i][j] = fmaf(a[i], bb[j], acc[i][j]);
        }
        __syncthreads();
    }

    // tf32-rounded: feeds proj GEMM A operand
    float* o = g_ao + ((size_t)b * NT + q0) * ND + h * NHD;
#pragma unroll
    for (int i = 0; i < 4; i++)
#pragma unroll
        for (int j = 0; j < 4; j++)
            o[(size_t)(ty * 4 + i) * ND + tx * 4 + j] = tf32r(acc[i][j]);
}

// ---------------------------------------------------------------------------
// Host driver — kernel launches only (graph-capturable)
// ---------------------------------------------------------------------------
extern "C" void kernel_launch(void* const* d_in, const int* in_sizes, int n_in,
                              void* d_out, int out_size) {
    const int*   idx   = (const int*)  d_in[0];
    const float* wte   = (const float*)d_in[1];
    const float* pos   = (const float*)d_in[2];
    const float* ln1g  = (const float*)d_in[3];
    const float* ln1b  = (const float*)d_in[4];
    const float* qkvw  = (const float*)d_in[5];
    const float* qkvb  = (const float*)d_in[6];
    const float* projw = (const float*)d_in[7];
    const float* projb = (const float*)d_in[8];
    const float* ln2g  = (const float*)d_in[9];
    const float* ln2b  = (const float*)d_in[10];
    const float* fc1w  = (const float*)d_in[11];
    const float* fc1b  = (const float*)d_in[12];
    const float* fc2w  = (const float*)d_in[13];
    const float* fc2b  = (const float*)d_in[14];
    const float* lnfg  = (const float*)d_in[15];
    const float* lnfb  = (const float*)d_in[16];

    float *px, *ph, *pao, *pfc1, *pqkv;
    float *pwteT, *pqkvT, *pprojT, *pfc1T, *pfc2T;
    cudaGetSymbolAddress((void**)&px,    g_x);
    cudaGetSymbolAddress((void**)&ph,    g_h);
    cudaGetSymbolAddress((void**)&pao,   g_ao);
    cudaGetSymbolAddress((void**)&pfc1,  g_fc1);
    cudaGetSymbolAddress((void**)&pqkv,  g_qkv);
    cudaGetSymbolAddress((void**)&pwteT, g_wteT);
    cudaGetSymbolAddress((void**)&pqkvT, g_qkvT);
    cudaGetSymbolAddress((void**)&pprojT,g_projT);
    cudaGetSymbolAddress((void**)&pfc1T, g_fc1T);
    cudaGetSymbolAddress((void**)&pfc2T, g_fc2T);

    cudaFuncSetAttribute(tc_gemm_k<0>, cudaFuncAttributeMaxDynamicSharedMemorySize, SMEM_GEMM);
    cudaFuncSetAttribute(tc_gemm_k<1>, cudaFuncAttributeMaxDynamicSharedMemorySize, SMEM_GEMM);
    cudaFuncSetAttribute(tc_gemm_k<2>, cudaFuncAttributeMaxDynamicSharedMemorySize, SMEM_GEMM);
    cudaFuncSetAttribute(tc_gemm_k<3>, cudaFuncAttributeMaxDynamicSharedMemorySize, SMEM_GEMM);

    // ---- weight prep (every replay; deterministic) ----
    wte_cvt_k<<<(int)(((size_t)NVP * ND + 255) / 256), 256>>>(wte);
    transpose_cvt_k<<<dim3(N3D / 32, ND / 32, NL), 256>>>(
        qkvw, pqkvT, ND, N3D, (size_t)ND * N3D, (size_t)N3D * ND);
    transpose_cvt_k<<<dim3(ND / 32, ND / 32, NL), 256>>>(
        projw, pprojT, ND, ND, (size_t)ND * ND, (size_t)ND * ND);
    transpose_cvt_k<<<dim3(N4D / 32, ND / 32, NL), 256>>>(
        fc1w, pfc1T, ND, N4D, (size_t)ND * N4D, (size_t)N4D * ND);
    transpose_cvt_k<<<dim3(ND / 32, N4D / 32, NL), 256>>>(
        fc2w, pfc2T, N4D, ND, (size_t)N4D * ND, (size_t)ND * N4D);

    embed_k<<<(NTOK * ND + 255) / 256, 256>>>(idx, wte, pos);

    for (int l = 0; l < NL; l++) {
        // --- attention half ---
        ln_k<<<NTOK, 256>>>(px, ln1g + (size_t)l * ND, ln1b + (size_t)l * ND, ph);

        tc_gemm_k<0><<<dim3(N3D / 128, NTOK / 128), 256, SMEM_GEMM>>>(
            ph, pqkvT + (size_t)l * N3D * ND, qkvb + (size_t)l * N3D,
            nullptr, pqkv, N3D, ND);

        dim3 gs(NT / 64, NT / 64, NB * NH);
        attn_scores_k<<<gs, 256>>>();
        attn_softmax_k<<<NB * NH * NT, 256>>>();
        dim3 ga(NT / 64, NB * NH);
        attn_av_k<<<ga, 256>>>();

        tc_gemm_k<1><<<dim3(ND / 128, NTOK / 128), 256, SMEM_GEMM>>>(
            pao, pprojT + (size_t)l * ND * ND, projb + (size_t)l * ND,
            px, px, ND, ND);

        // --- MLP half ---
        ln_k<<<NTOK, 256>>>(px, ln2g + (size_t)l * ND, ln2b + (size_t)l * ND, ph);

        tc_gemm_k<2><<<dim3(N4D / 128, NTOK / 128), 256, SMEM_GEMM>>>(
            ph, pfc1T + (size_t)l * N4D * ND, fc1b + (size_t)l * N4D,
            nullptr, pfc1, N4D, ND);

        tc_gemm_k<1><<<dim3(ND / 128, NTOK / 128), 256, SMEM_GEMM>>>(
            pfc1, pfc2T + (size_t)l * ND * N4D, fc2b + (size_t)l * ND,
            px, px, ND, N4D);
    }

    // final LN + tied head
    ln_k<<<NTOK, 256>>>(px, lnfg, lnfb, ph);
    tc_gemm_k<3><<<dim3(NVP / 128, NTOK / 128), 256, SMEM_GEMM>>>(
        ph, pwteT, nullptr, nullptr, (float*)d_out, NV, ND);
}

// round 8
// speedup vs baseline: 4.5526x; 1.2715x over previous
#include <cuda_runtime.h>
#include <math.h>
#include <stdint.h>

// GPT-2 small config (fixed by the problem)
#define NB   2
#define NT   1024
#define ND   768
#define NH   12
#define NL   12
#define NV   50257
#define NVP  50304                // NV padded to multiple of 128
#define NHD  64
#define NTOK (NB * NT)            // 2048 token rows
#define N3D  (3 * ND)             // 2304
#define N4D  (4 * ND)             // 3072

// ---------------------------------------------------------------------------
// Scratch (device globals; allocation inside kernel_launch is forbidden)
// ---------------------------------------------------------------------------
__device__ float g_x  [NTOK * ND];
__device__ float g_h  [NTOK * ND];          // LN out (tf32-rounded)
__device__ float g_qkv[NTOK * N3D];         // tf32-rounded
__device__ float g_ao [NTOK * ND];          // attn out (tf32-rounded)
__device__ float g_fc1[NTOK * N4D];         // GELU out (tf32-rounded)
__device__ float g_att[(size_t)NB * NH * NT * NT];      // ~100MB

// tf32 weights, transposed to [N,K] so GEMM B-operand is K-major like A
__device__ float g_wteT [(size_t)NVP * ND];             // rows >= NV zeroed
__device__ float g_qkvT [(size_t)NL * N3D * ND];
__device__ float g_projT[(size_t)NL * ND * ND];
__device__ float g_fc1T [(size_t)NL * N4D * ND];
__device__ float g_fc2T [(size_t)NL * ND * N4D];

// ---------------------------------------------------------------------------
// Helpers
// ---------------------------------------------------------------------------
__device__ __forceinline__ uint32_t smem_u32(const void* p) {
    uint32_t a;
    asm("{ .reg .u64 t; cvta.to.shared.u64 t, %1; cvt.u32.u64 %0, t; }"
        : "=r"(a) : "l"(p));
    return a;
}
__device__ __forceinline__ float tf32r(float x) {   // round-to-nearest tf32
    uint32_t r;
    asm("cvt.rna.tf32.f32 %0, %1;" : "=r"(r) : "f"(x));
    return __uint_as_float(r);
}
__device__ __forceinline__ void cp16(uint32_t dst, const void* src) {
    asm volatile("cp.async.cg.shared.global [%0], [%1], 16;"
                 :: "r"(dst), "l"(src) : "memory");
}
__device__ __forceinline__ void mma_tf32(float* c, const uint32_t* a,
                                         const uint32_t* b) {
    asm volatile(
        "mma.sync.aligned.m16n8k8.row.col.f32.tf32.tf32.f32 "
        "{%0,%1,%2,%3}, {%4,%5,%6,%7}, {%8,%9}, {%0,%1,%2,%3};"
        : "+f"(c[0]), "+f"(c[1]), "+f"(c[2]), "+f"(c[3])
        : "r"(a[0]), "r"(a[1]), "r"(a[2]), "r"(a[3]), "r"(b[0]), "r"(b[1]));
}
__device__ __forceinline__ float gelu_f(float v) {
    return 0.5f * v * (1.0f + erff(v * 0.70710678118654752f));
}

// smem: two stages, each stage = A tile + B tile, tile = 128 rows x 144B pitch
#define TILE_B   (128 * 144)
#define SA_ST(s) ((s) * 2 * TILE_B)
#define SB_ST(s) ((s) * 2 * TILE_B + TILE_B)
#define SMEM_GEMM (4 * TILE_B)      // 73728 B

// ---------------------------------------------------------------------------
// tf32 mma.sync GEMM: C[M,N] = A[M,K] @ W  (Bt = W^T as [N,K], rows padded)
//   A must already be tf32-rounded.
//   EPI: 0 +bias, tf32-rounded out (qkv); 1 +bias+res; 2 +bias+GELU (tf32
//   out); 3 none.
// Grid (ceil(N/128), M/128), 256 threads. K%32==0, K/32>=2, M%128==0.
// ---------------------------------------------------------------------------
template <int EPI>
__global__ __launch_bounds__(256, 2) void tc_gemm_k(
    const float* __restrict__ A, const float* __restrict__ Bt,
    const float* __restrict__ bias, const float* __restrict__ res,
    float* __restrict__ C, int N, int K)
{
    extern __shared__ char smem[];
    const uint32_t sb = smem_u32(smem);
    const int tid  = threadIdx.x;
    const int lane = tid & 31;
    const int wid  = tid >> 5;
    const int wm   = (wid >> 2) * 64;   // warp m-offset (2 rows of warps)
    const int wn   = (wid & 3) * 32;    // warp n-offset (4 cols of warps)
    const int bm   = blockIdx.y * 128;
    const int bn   = blockIdx.x * 128;
    const int g    = lane >> 2;         // 0..7
    const int t    = lane & 3;          // 0..3
    const int T    = K >> 5;            // BK=32 steps

    auto load_stage = [&](int step, int s) {
        const float* Ap = A  + (size_t)bm * K + step * 32;
        const float* Bp = Bt + (size_t)bn * K + step * 32;
#pragma unroll
        for (int i = 0; i < 4; i++) {
            int f = tid + i * 256;      // 1024 16B-chunks per operand
            int r = f >> 3, c = f & 7;
            cp16(sb + SA_ST(s) + r * 144 + c * 16, Ap + (size_t)r * K + c * 4);
            cp16(sb + SB_ST(s) + r * 144 + c * 16, Bp + (size_t)r * K + c * 4);
        }
        asm volatile("cp.async.commit_group;" ::: "memory");
    };

    float acc[4][4][4];                 // [mi][ni][frag]
#pragma unroll
    for (int i = 0; i < 4; i++)
#pragma unroll
        for (int j = 0; j < 4; j++)
#pragma unroll
            for (int r = 0; r < 4; r++) acc[i][j][r] = 0.0f;

    load_stage(0, 0);
    load_stage(1, 1);

    for (int ts = 0; ts < T; ts++) {
        const int s = ts & 1;
        if (ts + 1 < T) asm volatile("cp.async.wait_group 1;" ::: "memory");
        else            asm volatile("cp.async.wait_group 0;" ::: "memory");
        __syncthreads();

        const float* sa = (const float*)(smem + SA_ST(s));
        const float* sbb = (const float*)(smem + SB_ST(s));
#pragma unroll
        for (int kk = 0; kk < 4; kk++) {
            const int col = kk * 8 + t;
            uint32_t af[4][4], bf[4][2];
#pragma unroll
            for (int mi = 0; mi < 4; mi++) {
                const float* b0 = sa + (wm + mi * 16) * 36;
                af[mi][0] = __float_as_uint(b0[(g)     * 36 + col]);
                af[mi][1] = __float_as_uint(b0[(g + 8) * 36 + col]);
                af[mi][2] = __float_as_uint(b0[(g)     * 36 + col + 4]);
                af[mi][3] = __float_as_uint(b0[(g + 8) * 36 + col + 4]);
            }
#pragma unroll
            for (int ni = 0; ni < 4; ni++) {
                const float* b0 = sbb + (wn + ni * 8) * 36;
                bf[ni][0] = __float_as_uint(b0[g * 36 + col]);
                bf[ni][1] = __float_as_uint(b0[g * 36 + col + 4]);
            }
#pragma unroll
            for (int mi = 0; mi < 4; mi++)
#pragma unroll
                for (int ni = 0; ni < 4; ni++)
                    mma_tf32(acc[mi][ni], af[mi], bf[ni]);
        }
        __syncthreads();
        if (ts + 2 < T) load_stage(ts + 2, s);
    }

    // Epilogue: fragment-direct stores (2-float contiguous per lane)
#pragma unroll
    for (int mi = 0; mi < 4; mi++) {
#pragma unroll
        for (int ni = 0; ni < 4; ni++) {
            const int gn = bn + wn + ni * 8 + t * 2;
#pragma unroll
            for (int r = 0; r < 2; r++) {
                const int gm = bm + wm + mi * 16 + g + r * 8;
                float v0 = acc[mi][ni][r * 2 + 0];
                float v1 = acc[mi][ni][r * 2 + 1];
                if (EPI != 3) {
                    v0 += bias[gn];
                    v1 += bias[gn + 1];
                }
                if (EPI == 1) {
                    v0 += res[(size_t)gm * N + gn];
                    v1 += res[(size_t)gm * N + gn + 1];
                }
                if (EPI == 2) {
                    v0 = tf32r(gelu_f(v0));
                    v1 = tf32r(gelu_f(v1));
                }
                if (EPI == 0) {       // qkv: round so attention mma sees tf32
                    v0 = tf32r(v0);
                    v1 = tf32r(v1);
                }
                if (gn < N)     C[(size_t)gm * N + gn]     = v0;
                if (gn + 1 < N) C[(size_t)gm * N + gn + 1] = v1;
            }
        }
    }
}

// ---------------------------------------------------------------------------
// Weight prep: transpose [K,N] -> [N,K] with tf32 rounding (layer via z)
// ---------------------------------------------------------------------------
__global__ __launch_bounds__(256) void transpose_cvt_k(
    const float* __restrict__ in, float* __restrict__ out,
    int Kd, int Nd, size_t in_ls, size_t out_ls)
{
    __shared__ float t[32][33];
    const float* ip = in  + blockIdx.z * in_ls;
    float*       op = out + blockIdx.z * out_ls;
    int n0 = blockIdx.x * 32, k0 = blockIdx.y * 32;
    int tx = threadIdx.x & 31, ty = threadIdx.x >> 5;   // 32 x 8
#pragma unroll
    for (int i = 0; i < 32; i += 8)
        t[ty + i][tx] = ip[(size_t)(k0 + ty + i) * Nd + n0 + tx];
    __syncthreads();
#pragma unroll
    for (int i = 0; i < 32; i += 8)
        op[(size_t)(n0 + ty + i) * Kd + k0 + tx] = tf32r(t[tx][ty + i]);
}

__global__ __launch_bounds__(256) void wte_cvt_k(const float* __restrict__ wte) {
    size_t i = (size_t)blockIdx.x * 256 + threadIdx.x;
    if (i >= (size_t)NVP * ND) return;
    int n = (int)(i / ND);
    g_wteT[i] = (n < NV) ? tf32r(wte[i]) : 0.0f;
}

// ---------------------------------------------------------------------------
// Embedding
// ---------------------------------------------------------------------------
__global__ __launch_bounds__(256) void embed_k(const int* __restrict__ idx,
                                               const float* __restrict__ wte,
                                               const float* __restrict__ pos) {
    int i = blockIdx.x * 256 + threadIdx.x;
    if (i >= NTOK * ND) return;
    int tok = i / ND;
    int d   = i - tok * ND;
    int t   = tok & (NT - 1);
    g_x[i] = wte[(size_t)idx[tok] * ND + d] + pos[t * ND + d];
}

// ---------------------------------------------------------------------------
// LayerNorm: one block per token row; output tf32-rounded (feeds mma GEMMs)
// ---------------------------------------------------------------------------
__global__ __launch_bounds__(256) void ln_k(const float* __restrict__ in,
                                            const float* __restrict__ gamma,
                                            const float* __restrict__ beta,
                                            float* __restrict__ out) {
    int row = blockIdx.x;
    int tid = threadIdx.x;
    const float* x = in + (size_t)row * ND;
    float v0 = x[tid], v1 = x[tid + 256], v2 = x[tid + 512];

    __shared__ float red[256];
    __shared__ float s_mean, s_inv;

    red[tid] = v0 + v1 + v2;
    __syncthreads();
    for (int off = 128; off > 0; off >>= 1) {
        if (tid < off) red[tid] += red[tid + off];
        __syncthreads();
    }
    if (tid == 0) s_mean = red[0] * (1.0f / ND);
    __syncthreads();
    float m  = s_mean;
    float d0 = v0 - m, d1 = v1 - m, d2 = v2 - m;

    red[tid] = d0 * d0 + d1 * d1 + d2 * d2;
    __syncthreads();
    for (int off = 128; off > 0; off >>= 1) {
        if (tid < off) red[tid] += red[tid + off];
        __syncthreads();
    }
    if (tid == 0) s_inv = rsqrtf(red[0] * (1.0f / ND) + 1e-5f);
    __syncthreads();
    float inv = s_inv;

    float* o = out + (size_t)row * ND;
    o[tid]       = tf32r(d0 * inv * gamma[tid]       + beta[tid]);
    o[tid + 256] = tf32r(d1 * inv * gamma[tid + 256] + beta[tid + 256]);
    o[tid + 512] = tf32r(d2 * inv * gamma[tid + 512] + beta[tid + 512]);
}

// ---------------------------------------------------------------------------
// Attention scores via mma: S[64q x 64k] = Q.K^T * 0.125
// 128 threads = 4 warps, each warp 16 q-rows x 64 k-cols.
// Pitch 68 floats: fragment bank = (4g+t)%32 -> conflict-free.
// ---------------------------------------------------------------------------
__global__ __launch_bounds__(128) void attn_scores_k() {
    int bh = blockIdx.z;
    int b  = bh / NH;
    int h  = bh - b * NH;
    int q0 = blockIdx.y * 64;
    int k0 = blockIdx.x * 64;
    if (k0 > q0) return;

    __shared__ float Qs[64][68];
    __shared__ float Ks[64][68];
    const uint32_t sq = smem_u32(Qs);
    const uint32_t sk = smem_u32(Ks);
    const int tid = threadIdx.x;
    const float* base = g_qkv + (size_t)b * NT * N3D + h * NHD;

#pragma unroll
    for (int i = 0; i < 8; i++) {
        int f = tid + i * 128;          // 1024 16B chunks per tile
        int r = f >> 4, c = f & 15;
        cp16(sq + (r * 68 + c * 4) * 4, base + (size_t)(q0 + r) * N3D + c * 4);
        cp16(sk + (r * 68 + c * 4) * 4, base + (size_t)(k0 + r) * N3D + ND + c * 4);
    }
    asm volatile("cp.async.commit_group;" ::: "memory");
    asm volatile("cp.async.wait_group 0;" ::: "memory");
    __syncthreads();

    const int lane = tid & 31, wid = tid >> 5;
    const int g = lane >> 2, t = lane & 3;
    const int wm = wid * 16;

    float acc[8][4];
#pragma unroll
    for (int i = 0; i < 8; i++)
#pragma unroll
        for (int r = 0; r < 4; r++) acc[i][r] = 0.0f;

#pragma unroll
    for (int kk = 0; kk < 8; kk++) {
        const int col = kk * 8 + t;
        uint32_t af[4];
        af[0] = __float_as_uint(Qs[wm + g][col]);
        af[1] = __float_as_uint(Qs[wm + g + 8][col]);
        af[2] = __float_as_uint(Qs[wm + g][col + 4]);
        af[3] = __float_as_uint(Qs[wm + g + 8][col + 4]);
#pragma unroll
        for (int ni = 0; ni < 8; ni++) {
            uint32_t bf[2];
            bf[0] = __float_as_uint(Ks[ni * 8 + g][col]);
            bf[1] = __float_as_uint(Ks[ni * 8 + g][col + 4]);
            mma_tf32(acc[ni], af, bf);
        }
    }

    float* S = g_att + ((size_t)bh * NT + q0) * NT + k0;
#pragma unroll
    for (int ni = 0; ni < 8; ni++) {
        const int cn = ni * 8 + t * 2;
#pragma unroll
        for (int r = 0; r < 2; r++) {
            const int rm = wm + g + r * 8;
            S[(size_t)rm * NT + cn]     = acc[ni][r * 2 + 0] * 0.125f;
            S[(size_t)rm * NT + cn + 1] = acc[ni][r * 2 + 1] * 0.125f;
        }
    }
}

// ---------------------------------------------------------------------------
// Causal softmax; probs tf32-rounded (feed PV mma); zeros written only up to
// the end of the diagonal 64-tile (all attn_av_k ever reads).
// ---------------------------------------------------------------------------
__global__ __launch_bounds__(256) void attn_softmax_k() {
    int row = blockIdx.x;
    int tid = threadIdx.x;
    int q   = row & (NT - 1);
    float* S = g_att + (size_t)row * NT;

    __shared__ float red[256];

    float mx = -1e30f;
    for (int k = tid; k <= q; k += 256) mx = fmaxf(mx, S[k]);
    red[tid] = mx;
    __syncthreads();
    for (int off = 128; off > 0; off >>= 1) {
        if (tid < off) red[tid] = fmaxf(red[tid], red[tid + off]);
        __syncthreads();
    }
    mx = red[0];
    __syncthreads();

    float sum = 0.0f;
    for (int k = tid; k <= q; k += 256) {
        float e = __expf(S[k] - mx);
        S[k] = e;
        sum += e;
    }
    red[tid] = sum;
    __syncthreads();
    for (int off = 128; off > 0; off >>= 1) {
        if (tid < off) red[tid] += red[tid + off];
        __syncthreads();
    }
    float inv = 1.0f / red[0];

    int kend = ((q >> 6) + 1) << 6;     // end of diagonal 64-tile
    for (int k = tid; k < kend; k += 256)
        S[k] = (k <= q) ? tf32r(S[k] * inv) : 0.0f;
}

// ---------------------------------------------------------------------------
// O = P @ V via mma: per block 64 q-rows x 64 dims, k-loop to diagonal.
// Ps pitch 68 (A-frag conflict-free), Vs pitch 72 (B-frag bank = 8t+g).
// ---------------------------------------------------------------------------
__global__ __launch_bounds__(128) void attn_av_k() {
    int bh = blockIdx.y;
    int b  = bh / NH;
    int h  = bh - b * NH;
    int q0 = blockIdx.x * 64;

    __shared__ float Ps[64][68];
    __shared__ float Vs[64][72];
    const uint32_t sp = smem_u32(Ps);
    const uint32_t sv = smem_u32(Vs);
    const int tid = threadIdx.x;
    const float* P     = g_att + ((size_t)bh * NT + q0) * NT;
    const float* vbase = g_qkv + (size_t)b * NT * N3D + 2 * ND + h * NHD;

    const int lane = tid & 31, wid = tid >> 5;
    const int g = lane >> 2, t = lane & 3;
    const int wm = wid * 16;

    float acc[8][4];
#pragma unroll
    for (int i = 0; i < 8; i++)
#pragma unroll
        for (int r = 0; r < 4; r++) acc[i][r] = 0.0f;

    for (int k0 = 0; k0 <= q0; k0 += 64) {
#pragma unroll
        for (int i = 0; i < 8; i++) {
            int f = tid + i * 128;
            int r = f >> 4, c = f & 15;
            cp16(sp + (r * 68 + c * 4) * 4, P + (size_t)r * NT + k0 + c * 4);
            cp16(sv + (r * 72 + c * 4) * 4, vbase + (size_t)(k0 + r) * N3D + c * 4);
        }
        asm volatile("cp.async.commit_group;" ::: "memory");
        asm volatile("cp.async.wait_group 0;" ::: "memory");
        __syncthreads();

#pragma unroll
        for (int kk = 0; kk < 8; kk++) {
            const int col = kk * 8 + t;
            uint32_t af[4];
            af[0] = __float_as_uint(Ps[wm + g][col]);
            af[1] = __float_as_uint(Ps[wm + g + 8][col]);
            af[2] = __float_as_uint(Ps[wm + g][col + 4]);
            af[3] = __float_as_uint(Ps[wm + g + 8][col + 4]);
#pragma unroll
            for (int ni = 0; ni < 8; ni++) {
                uint32_t bf[2];
                bf[0] = __float_as_uint(Vs[col][ni * 8 + g]);
                bf[1] = __float_as_uint(Vs[col + 4][ni * 8 + g]);
                mma_tf32(acc[ni], af, bf);
            }
        }
        __syncthreads();
    }

    // tf32-rounded: feeds proj GEMM A operand
    float* o = g_ao + ((size_t)b * NT + q0) * ND + h * NHD;
#pragma unroll
    for (int ni = 0; ni < 8; ni++) {
        const int cn = ni * 8 + t * 2;
#pragma unroll
        for (int r = 0; r < 2; r++) {
            const int rm = wm + g + r * 8;
            o[(size_t)rm * ND + cn]     = tf32r(acc[ni][r * 2 + 0]);
            o[(size_t)rm * ND + cn + 1] = tf32r(acc[ni][r * 2 + 1]);
        }
    }
}

// ---------------------------------------------------------------------------
// Host driver — kernel launches only (graph-capturable)
// ---------------------------------------------------------------------------
extern "C" void kernel_launch(void* const* d_in, const int* in_sizes, int n_in,
                              void* d_out, int out_size) {
    const int*   idx   = (const int*)  d_in[0];
    const float* wte   = (const float*)d_in[1];
    const float* pos   = (const float*)d_in[2];
    const float* ln1g  = (const float*)d_in[3];
    const float* ln1b  = (const float*)d_in[4];
    const float* qkvw  = (const float*)d_in[5];
    const float* qkvb  = (const float*)d_in[6];
    const float* projw = (const float*)d_in[7];
    const float* projb = (const float*)d_in[8];
    const float* ln2g  = (const float*)d_in[9];
    const float* ln2b  = (const float*)d_in[10];
    const float* fc1w  = (const float*)d_in[11];
    const float* fc1b  = (const float*)d_in[12];
    const float* fc2w  = (const float*)d_in[13];
    const float* fc2b  = (const float*)d_in[14];
    const float* lnfg  = (const float*)d_in[15];
    const float* lnfb  = (const float*)d_in[16];

    float *px, *ph, *pao, *pfc1, *pqkv;
    float *pwteT, *pqkvT, *pprojT, *pfc1T, *pfc2T;
    cudaGetSymbolAddress((void**)&px,    g_x);
    cudaGetSymbolAddress((void**)&ph,    g_h);
    cudaGetSymbolAddress((void**)&pao,   g_ao);
    cudaGetSymbolAddress((void**)&pfc1,  g_fc1);
    cudaGetSymbolAddress((void**)&pqkv,  g_qkv);
    cudaGetSymbolAddress((void**)&pwteT, g_wteT);
    cudaGetSymbolAddress((void**)&pqkvT, g_qkvT);
    cudaGetSymbolAddress((void**)&pprojT,g_projT);
    cudaGetSymbolAddress((void**)&pfc1T, g_fc1T);
    cudaGetSymbolAddress((void**)&pfc2T, g_fc2T);

    cudaFuncSetAttribute(tc_gemm_k<0>, cudaFuncAttributeMaxDynamicSharedMemorySize, SMEM_GEMM);
    cudaFuncSetAttribute(tc_gemm_k<1>, cudaFuncAttributeMaxDynamicSharedMemorySize, SMEM_GEMM);
    cudaFuncSetAttribute(tc_gemm_k<2>, cudaFuncAttributeMaxDynamicSharedMemorySize, SMEM_GEMM);
    cudaFuncSetAttribute(tc_gemm_k<3>, cudaFuncAttributeMaxDynamicSharedMemorySize, SMEM_GEMM);

    // ---- weight prep (every replay; deterministic) ----
    wte_cvt_k<<<(int)(((size_t)NVP * ND + 255) / 256), 256>>>(wte);
    transpose_cvt_k<<<dim3(N3D / 32, ND / 32, NL), 256>>>(
        qkvw, pqkvT, ND, N3D, (size_t)ND * N3D, (size_t)N3D * ND);
    transpose_cvt_k<<<dim3(ND / 32, ND / 32, NL), 256>>>(
        projw, pprojT, ND, ND, (size_t)ND * ND, (size_t)ND * ND);
    transpose_cvt_k<<<dim3(N4D / 32, ND / 32, NL), 256>>>(
        fc1w, pfc1T, ND, N4D, (size_t)ND * N4D, (size_t)N4D * ND);
    transpose_cvt_k<<<dim3(ND / 32, N4D / 32, NL), 256>>>(
        fc2w, pfc2T, N4D, ND, (size_t)N4D * ND, (size_t)ND * N4D);

    embed_k<<<(NTOK * ND + 255) / 256, 256>>>(idx, wte, pos);

    for (int l = 0; l < NL; l++) {
        // --- attention half ---
        ln_k<<<NTOK, 256>>>(px, ln1g + (size_t)l * ND, ln1b + (size_t)l * ND, ph);

        tc_gemm_k<0><<<dim3(N3D / 128, NTOK / 128), 256, SMEM_GEMM>>>(
            ph, pqkvT + (size_t)l * N3D * ND, qkvb + (size_t)l * N3D,
            nullptr, pqkv, N3D, ND);

        dim3 gs(NT / 64, NT / 64, NB * NH);
        attn_scores_k<<<gs, 128>>>();
        attn_softmax_k<<<NB * NH * NT, 256>>>();
        dim3 ga(NT / 64, NB * NH);
        attn_av_k<<<ga, 128>>>();

        tc_gemm_k<1><<<dim3(ND / 128, NTOK / 128), 256, SMEM_GEMM>>>(
            pao, pprojT + (size_t)l * ND * ND, projb + (size_t)l * ND,
            px, px, ND, ND);

        // --- MLP half ---
        ln_k<<<NTOK, 256>>>(px, ln2g + (size_t)l * ND, ln2b + (size_t)l * ND, ph);

        tc_gemm_k<2><<<dim3(N4D / 128, NTOK / 128), 256, SMEM_GEMM>>>(
            ph, pfc1T + (size_t)l * N4D * ND, fc1b + (size_t)l * N4D,
            nullptr, pfc1, N4D, ND);

        tc_gemm_k<1><<<dim3(ND / 128, NTOK / 128), 256, SMEM_GEMM>>>(
            pfc1, pfc2T + (size_t)l * ND * N4D, fc2b + (size_t)l * ND,
            px, px, ND, N4D);
    }

    // final LN + tied head
    ln_k<<<NTOK, 256>>>(px, lnfg, lnfb, ph);
    tc_gemm_k<3><<<dim3(NVP / 128, NTOK / 128), 256, SMEM_GEMM>>>(
        ph, pwteT, nullptr, nullptr, (float*)d_out, NV, ND);
}

// round 9
// speedup vs baseline: 5.1773x; 1.1372x over previous
#include <cuda_runtime.h>
#include <math.h>
#include <stdint.h>

// GPT-2 small config (fixed by the problem)
#define NB   2
#define NT   1024
#define ND   768
#define NH   12
#define NL   12
#define NV   50257
#define NVP  50304                // NV padded to multiple of 128
#define NHD  64
#define NTOK (NB * NT)            // 2048 token rows
#define N3D  (3 * ND)             // 2304
#define N4D  (4 * ND)             // 3072

// ---------------------------------------------------------------------------
// Scratch (device globals; allocation inside kernel_launch is forbidden)
// ---------------------------------------------------------------------------
__device__ float g_x  [NTOK * ND];
__device__ float g_h  [NTOK * ND];          // LN out (tf32-rounded)
__device__ float g_qkv[NTOK * N3D];         // tf32-rounded
__device__ float g_ao [NTOK * ND];          // attn out (tf32-rounded)
__device__ float g_fc1[NTOK * N4D];         // GELU out (tf32-rounded)

// tf32 weights, transposed to [N,K] so GEMM B-operand is K-major like A
__device__ float g_wteT [(size_t)NVP * ND];             // rows >= NV zeroed
__device__ float g_qkvT [(size_t)NL * N3D * ND];
__device__ float g_projT[(size_t)NL * ND * ND];
__device__ float g_fc1T [(size_t)NL * N4D * ND];
__device__ float g_fc2T [(size_t)NL * ND * N4D];

// ---------------------------------------------------------------------------
// Helpers
// ---------------------------------------------------------------------------
__device__ __forceinline__ uint32_t smem_u32(const void* p) {
    uint32_t a;
    asm("{ .reg .u64 t; cvta.to.shared.u64 t, %1; cvt.u32.u64 %0, t; }"
        : "=r"(a) : "l"(p));
    return a;
}
__device__ __forceinline__ float tf32r(float x) {   // round-to-nearest tf32
    uint32_t r;
    asm("cvt.rna.tf32.f32 %0, %1;" : "=r"(r) : "f"(x));
    return __uint_as_float(r);
}
__device__ __forceinline__ void cp16(uint32_t dst, const void* src) {
    asm volatile("cp.async.cg.shared.global [%0], [%1], 16;"
                 :: "r"(dst), "l"(src) : "memory");
}
__device__ __forceinline__ void mma_tf32(float* c, const uint32_t* a,
                                         const uint32_t* b) {
    asm volatile(
        "mma.sync.aligned.m16n8k8.row.col.f32.tf32.tf32.f32 "
        "{%0,%1,%2,%3}, {%4,%5,%6,%7}, {%8,%9}, {%0,%1,%2,%3};"
        : "+f"(c[0]), "+f"(c[1]), "+f"(c[2]), "+f"(c[3])
        : "r"(a[0]), "r"(a[1]), "r"(a[2]), "r"(a[3]), "r"(b[0]), "r"(b[1]));
}
__device__ __forceinline__ float gelu_f(float v) {
    return 0.5f * v * (1.0f + erff(v * 0.70710678118654752f));
}

// smem: two stages, each stage = A tile + B tile, tile = 128 rows x 144B pitch
#define TILE_B   (128 * 144)
#define SA_ST(s) ((s) * 2 * TILE_B)
#define SB_ST(s) ((s) * 2 * TILE_B + TILE_B)
#define SMEM_GEMM (4 * TILE_B)      // 73728 B

// ---------------------------------------------------------------------------
// tf32 mma.sync GEMM: C[M,N] = A[M,K] @ W  (Bt = W^T as [N,K], rows padded)
//   A must already be tf32-rounded.
//   EPI: 0 +bias, tf32 out (qkv); 1 +bias+res; 2 +bias+GELU (tf32 out); 3 none
// Grid (ceil(N/128), M/128), 256 threads. K%32==0, K/32>=2, M%128==0.
// ---------------------------------------------------------------------------
template <int EPI>
__global__ __launch_bounds__(256, 2) void tc_gemm_k(
    const float* __restrict__ A, const float* __restrict__ Bt,
    const float* __restrict__ bias, const float* __restrict__ res,
    float* __restrict__ C, int N, int K)
{
    extern __shared__ char smem[];
    const uint32_t sb = smem_u32(smem);
    const int tid  = threadIdx.x;
    const int lane = tid & 31;
    const int wid  = tid >> 5;
    const int wm   = (wid >> 2) * 64;
    const int wn   = (wid & 3) * 32;
    const int bm   = blockIdx.y * 128;
    const int bn   = blockIdx.x * 128;
    const int g    = lane >> 2;
    const int t    = lane & 3;
    const int T    = K >> 5;

    auto load_stage = [&](int step, int s) {
        const float* Ap = A  + (size_t)bm * K + step * 32;
        const float* Bp = Bt + (size_t)bn * K + step * 32;
#pragma unroll
        for (int i = 0; i < 4; i++) {
            int f = tid + i * 256;
            int r = f >> 3, c = f & 7;
            cp16(sb + SA_ST(s) + r * 144 + c * 16, Ap + (size_t)r * K + c * 4);
            cp16(sb + SB_ST(s) + r * 144 + c * 16, Bp + (size_t)r * K + c * 4);
        }
        asm volatile("cp.async.commit_group;" ::: "memory");
    };

    float acc[4][4][4];
#pragma unroll
    for (int i = 0; i < 4; i++)
#pragma unroll
        for (int j = 0; j < 4; j++)
#pragma unroll
            for (int r = 0; r < 4; r++) acc[i][j][r] = 0.0f;

    load_stage(0, 0);
    load_stage(1, 1);

    for (int ts = 0; ts < T; ts++) {
        const int s = ts & 1;
        if (ts + 1 < T) asm volatile("cp.async.wait_group 1;" ::: "memory");
        else            asm volatile("cp.async.wait_group 0;" ::: "memory");
        __syncthreads();

        const float* sa = (const float*)(smem + SA_ST(s));
        const float* sbb = (const float*)(smem + SB_ST(s));
#pragma unroll
        for (int kk = 0; kk < 4; kk++) {
            const int col = kk * 8 + t;
            uint32_t af[4][4], bf[4][2];
#pragma unroll
            for (int mi = 0; mi < 4; mi++) {
                const float* b0 = sa + (wm + mi * 16) * 36;
                af[mi][0] = __float_as_uint(b0[(g)     * 36 + col]);
                af[mi][1] = __float_as_uint(b0[(g + 8) * 36 + col]);
                af[mi][2] = __float_as_uint(b0[(g)     * 36 + col + 4]);
                af[mi][3] = __float_as_uint(b0[(g + 8) * 36 + col + 4]);
            }
#pragma unroll
            for (int ni = 0; ni < 4; ni++) {
                const float* b0 = sbb + (wn + ni * 8) * 36;
                bf[ni][0] = __float_as_uint(b0[g * 36 + col]);
                bf[ni][1] = __float_as_uint(b0[g * 36 + col + 4]);
            }
#pragma unroll
            for (int mi = 0; mi < 4; mi++)
#pragma unroll
                for (int ni = 0; ni < 4; ni++)
                    mma_tf32(acc[mi][ni], af[mi], bf[ni]);
        }
        __syncthreads();
        if (ts + 2 < T) load_stage(ts + 2, s);
    }

#pragma unroll
    for (int mi = 0; mi < 4; mi++) {
#pragma unroll
        for (int ni = 0; ni < 4; ni++) {
            const int gn = bn + wn + ni * 8 + t * 2;
#pragma unroll
            for (int r = 0; r < 2; r++) {
                const int gm = bm + wm + mi * 16 + g + r * 8;
                float v0 = acc[mi][ni][r * 2 + 0];
                float v1 = acc[mi][ni][r * 2 + 1];
                if (EPI != 3) {
                    v0 += bias[gn];
                    v1 += bias[gn + 1];
                }
                if (EPI == 1) {
                    v0 += res[(size_t)gm * N + gn];
                    v1 += res[(size_t)gm * N + gn + 1];
                }
                if (EPI == 2) {
                    v0 = tf32r(gelu_f(v0));
                    v1 = tf32r(gelu_f(v1));
                }
                if (EPI == 0) {
                    v0 = tf32r(v0);
                    v1 = tf32r(v1);
                }
                if (gn < N)     C[(size_t)gm * N + gn]     = v0;
                if (gn + 1 < N) C[(size_t)gm * N + gn + 1] = v1;
            }
        }
    }
}

// ---------------------------------------------------------------------------
// Weight prep
// ---------------------------------------------------------------------------
__global__ __launch_bounds__(256) void transpose_cvt_k(
    const float* __restrict__ in, float* __restrict__ out,
    int Kd, int Nd, size_t in_ls, size_t out_ls)
{
    __shared__ float t[32][33];
    const float* ip = in  + blockIdx.z * in_ls;
    float*       op = out + blockIdx.z * out_ls;
    int n0 = blockIdx.x * 32, k0 = blockIdx.y * 32;
    int tx = threadIdx.x & 31, ty = threadIdx.x >> 5;
#pragma unroll
    for (int i = 0; i < 32; i += 8)
        t[ty + i][tx] = ip[(size_t)(k0 + ty + i) * Nd + n0 + tx];
    __syncthreads();
#pragma unroll
    for (int i = 0; i < 32; i += 8)
        op[(size_t)(n0 + ty + i) * Kd + k0 + tx] = tf32r(t[tx][ty + i]);
}

__global__ __launch_bounds__(256) void wte_cvt_k(const float* __restrict__ wte) {
    size_t i = (size_t)blockIdx.x * 256 + threadIdx.x;
    if (i >= (size_t)NVP * ND) return;
    int n = (int)(i / ND);
    g_wteT[i] = (n < NV) ? tf32r(wte[i]) : 0.0f;
}

// ---------------------------------------------------------------------------
// Embedding
// ---------------------------------------------------------------------------
__global__ __launch_bounds__(256) void embed_k(const int* __restrict__ idx,
                                               const float* __restrict__ wte,
                                               const float* __restrict__ pos) {
    int i = blockIdx.x * 256 + threadIdx.x;
    if (i >= NTOK * ND) return;
    int tok = i / ND;
    int d   = i - tok * ND;
    int t   = tok & (NT - 1);
    g_x[i] = wte[(size_t)idx[tok] * ND + d] + pos[t * ND + d];
}

// ---------------------------------------------------------------------------
// LayerNorm: single-pass (sum, sumsq) warp-shuffle reduction, 1 syncthreads.
// Output tf32-rounded (feeds mma GEMMs).
// ---------------------------------------------------------------------------
__global__ __launch_bounds__(256) void ln_k(const float* __restrict__ in,
                                            const float* __restrict__ gamma,
                                            const float* __restrict__ beta,
                                            float* __restrict__ out) {
    int row = blockIdx.x;
    int tid = threadIdx.x;
    int lane = tid & 31, wid = tid >> 5;
    const float* x = in + (size_t)row * ND;
    float v0 = x[tid], v1 = x[tid + 256], v2 = x[tid + 512];

    float s  = v0 + v1 + v2;
    float sq = v0 * v0 + v1 * v1 + v2 * v2;
#pragma unroll
    for (int off = 16; off > 0; off >>= 1) {
        s  += __shfl_down_sync(0xffffffffu, s,  off);
        sq += __shfl_down_sync(0xffffffffu, sq, off);
    }
    __shared__ float ws[8], wq[8];
    if (lane == 0) { ws[wid] = s; wq[wid] = sq; }
    __syncthreads();
    float S = 0.0f, Q = 0.0f;
#pragma unroll
    for (int i = 0; i < 8; i++) { S += ws[i]; Q += wq[i]; }
    float m   = S * (1.0f / ND);
    float var = Q * (1.0f / ND) - m * m;
    float inv = rsqrtf(var + 1e-5f);

    float* o = out + (size_t)row * ND;
    o[tid]       = tf32r((v0 - m) * inv * gamma[tid]       + beta[tid]);
    o[tid + 256] = tf32r((v1 - m) * inv * gamma[tid + 256] + beta[tid + 256]);
    o[tid + 512] = tf32r((v2 - m) * inv * gamma[tid + 512] + beta[tid + 512]);
}

// ---------------------------------------------------------------------------
// Fused flash attention: one block per (64 q-rows, head). Online softmax,
// no materialized attention matrix. 128 threads = 4 warps x 16 q-rows.
// Layouts (all bank-checked): Qs/Ks/Ps pitch 68, Vs pitch 72.
// ---------------------------------------------------------------------------
#define FQ_PITCH 68
#define FV_PITCH 72
#define FLASH_SMEM ((3 * 64 * FQ_PITCH + 64 * FV_PITCH) * 4)   // 70656 B

__global__ __launch_bounds__(128) void flash_attn_k() {
    int bh = blockIdx.y;
    int b  = bh / NH;
    int h  = bh - b * NH;
    int q0 = blockIdx.x * 64;

    extern __shared__ float fsm[];
    float* Qs = fsm;
    float* Ks = fsm + 64 * FQ_PITCH;
    float* Ps = fsm + 2 * 64 * FQ_PITCH;
    float* Vs = fsm + 3 * 64 * FQ_PITCH;
    const uint32_t sq = smem_u32(Qs);
    const uint32_t sk = smem_u32(Ks);
    const uint32_t sv = smem_u32(Vs);

    const int tid  = threadIdx.x;
    const int lane = tid & 31, wid = tid >> 5;
    const int g = lane >> 2, t = lane & 3;
    const int wm = wid * 16;

    const float* base = g_qkv + (size_t)b * NT * N3D + h * NHD;

    // Q tile (stays resident all iterations)
#pragma unroll
    for (int i = 0; i < 8; i++) {
        int f = tid + i * 128;
        int r = f >> 4, c = f & 15;
        cp16(sq + (r * FQ_PITCH + c * 4) * 4, base + (size_t)(q0 + r) * N3D + c * 4);
    }
    asm volatile("cp.async.commit_group;" ::: "memory");

    float acc[8][4];
#pragma unroll
    for (int i = 0; i < 8; i++)
#pragma unroll
        for (int r = 0; r < 4; r++) acc[i][r] = 0.0f;
    float m[2] = {-1e30f, -1e30f};
    float l[2] = {0.0f, 0.0f};

    for (int k0 = 0; k0 <= q0; k0 += 64) {
        __syncthreads();                    // prior-iteration Ks/Vs/Ps reads done
#pragma unroll
        for (int i = 0; i < 8; i++) {
            int f = tid + i * 128;
            int r = f >> 4, c = f & 15;
            cp16(sk + (r * FQ_PITCH + c * 4) * 4,
                 base + (size_t)(k0 + r) * N3D + ND + c * 4);
            cp16(sv + (r * FV_PITCH + c * 4) * 4,
                 base + (size_t)(k0 + r) * N3D + 2 * ND + c * 4);
        }
        asm volatile("cp.async.commit_group;" ::: "memory");
        asm volatile("cp.async.wait_group 0;" ::: "memory");
        __syncthreads();

        // S = Q.K^T
        float s[8][4];
#pragma unroll
        for (int i = 0; i < 8; i++)
#pragma unroll
            for (int r = 0; r < 4; r++) s[i][r] = 0.0f;
#pragma unroll
        for (int kk = 0; kk < 8; kk++) {
            const int col = kk * 8 + t;
            uint32_t af[4];
            af[0] = __float_as_uint(Qs[(wm + g) * FQ_PITCH + col]);
            af[1] = __float_as_uint(Qs[(wm + g + 8) * FQ_PITCH + col]);
            af[2] = __float_as_uint(Qs[(wm + g) * FQ_PITCH + col + 4]);
            af[3] = __float_as_uint(Qs[(wm + g + 8) * FQ_PITCH + col + 4]);
#pragma unroll
            for (int ni = 0; ni < 8; ni++) {
                uint32_t bf[2];
                bf[0] = __float_as_uint(Ks[(ni * 8 + g) * FQ_PITCH + col]);
                bf[1] = __float_as_uint(Ks[(ni * 8 + g) * FQ_PITCH + col + 4]);
                mma_tf32(s[ni], af, bf);
            }
        }

        // scale + causal mask (diagonal tile only)
        const bool diag = (k0 == q0);
#pragma unroll
        for (int ni = 0; ni < 8; ni++)
#pragma unroll
            for (int r = 0; r < 2; r++)
#pragma unroll
                for (int c = 0; c < 2; c++) {
                    float v = s[ni][r * 2 + c] * 0.125f;
                    if (diag && (ni * 8 + t * 2 + c) > (wm + g + 8 * r))
                        v = -1e30f;
                    s[ni][r * 2 + c] = v;
                }

        // per-row tile max (quad reduce over t)
        float mt[2] = {-1e30f, -1e30f};
#pragma unroll
        for (int ni = 0; ni < 8; ni++)
#pragma unroll
            for (int r = 0; r < 2; r++) {
                mt[r] = fmaxf(mt[r], fmaxf(s[ni][r * 2], s[ni][r * 2 + 1]));
            }
#pragma unroll
        for (int r = 0; r < 2; r++) {
            mt[r] = fmaxf(mt[r], __shfl_xor_sync(0xffffffffu, mt[r], 1));
            mt[r] = fmaxf(mt[r], __shfl_xor_sync(0xffffffffu, mt[r], 2));
        }

        float mn[2], sc[2], ls[2] = {0.0f, 0.0f};
#pragma unroll
        for (int r = 0; r < 2; r++) {
            mn[r] = fmaxf(m[r], mt[r]);
            sc[r] = __expf(m[r] - mn[r]);
        }

        // P = exp(S - mn), tf32-rounded; accumulate row sums
#pragma unroll
        for (int ni = 0; ni < 8; ni++)
#pragma unroll
            for (int r = 0; r < 2; r++)
#pragma unroll
                for (int c = 0; c < 2; c++) {
                    float p = tf32r(__expf(s[ni][r * 2 + c] - mn[r]));
                    s[ni][r * 2 + c] = p;
                    ls[r] += p;
                }
#pragma unroll
        for (int r = 0; r < 2; r++) {
            ls[r] += __shfl_xor_sync(0xffffffffu, ls[r], 1);
            ls[r] += __shfl_xor_sync(0xffffffffu, ls[r], 2);
            l[r] = l[r] * sc[r] + ls[r];
            m[r] = mn[r];
        }

        // rescale O accumulator
#pragma unroll
        for (int ni = 0; ni < 8; ni++)
#pragma unroll
            for (int r = 0; r < 2; r++) {
                acc[ni][r * 2]     *= sc[r];
                acc[ni][r * 2 + 1] *= sc[r];
            }

        // write P to smem (C-frag layout -> float2 stores)
#pragma unroll
        for (int ni = 0; ni < 8; ni++) {
            const int cn = ni * 8 + t * 2;
            *(float2*)&Ps[(wm + g) * FQ_PITCH + cn]     = make_float2(s[ni][0], s[ni][1]);
            *(float2*)&Ps[(wm + g + 8) * FQ_PITCH + cn] = make_float2(s[ni][2], s[ni][3]);
        }
        __syncthreads();

        // O += P.V
#pragma unroll
        for (int kk = 0; kk < 8; kk++) {
            const int col = kk * 8 + t;
            uint32_t af[4];
            af[0] = __float_as_uint(Ps[(wm + g) * FQ_PITCH + col]);
            af[1] = __float_as_uint(Ps[(wm + g + 8) * FQ_PITCH + col]);
            af[2] = __float_as_uint(Ps[(wm + g) * FQ_PITCH + col + 4]);
            af[3] = __float_as_uint(Ps[(wm + g + 8) * FQ_PITCH + col + 4]);
#pragma unroll
            for (int ni = 0; ni < 8; ni++) {
                uint32_t bf[2];
                bf[0] = __float_as_uint(Vs[col * FV_PITCH + ni * 8 + g]);
                bf[1] = __float_as_uint(Vs[(col + 4) * FV_PITCH + ni * 8 + g]);
                mma_tf32(acc[ni], af, bf);
            }
        }
    }

    // O /= l ; write tf32-rounded (feeds proj GEMM)
    float inv[2] = {1.0f / l[0], 1.0f / l[1]};
    float* o = g_ao + ((size_t)b * NT + q0) * ND + h * NHD;
#pragma unroll
    for (int ni = 0; ni < 8; ni++) {
        const int cn = ni * 8 + t * 2;
#pragma unroll
        for (int r = 0; r < 2; r++) {
            const int rm = wm + g + r * 8;
            float v0 = tf32r(acc[ni][r * 2 + 0] * inv[r]);
            float v1 = tf32r(acc[ni][r * 2 + 1] * inv[r]);
            *(float2*)&o[(size_t)rm * ND + cn] = make_float2(v0, v1);
        }
    }
}

// ---------------------------------------------------------------------------
// Host driver — kernel launches only (graph-capturable)
// ---------------------------------------------------------------------------
extern "C" void kernel_launch(void* const* d_in, const int* in_sizes, int n_in,
                              void* d_out, int out_size) {
    const int*   idx   = (const int*)  d_in[0];
    const float* wte   = (const float*)d_in[1];
    const float* pos   = (const float*)d_in[2];
    const float* ln1g  = (const float*)d_in[3];
    const float* ln1b  = (const float*)d_in[4];
    const float* qkvw  = (const float*)d_in[5];
    const float* qkvb  = (const float*)d_in[6];
    const float* projw = (const float*)d_in[7];
    const float* projb = (const float*)d_in[8];
    const float* ln2g  = (const float*)d_in[9];
    const float* ln2b  = (const float*)d_in[10];
    const float* fc1w  = (const float*)d_in[11];
    const float* fc1b  = (const float*)d_in[12];
    const float* fc2w  = (const float*)d_in[13];
    const float* fc2b  = (const float*)d_in[14];
    const float* lnfg  = (const float*)d_in[15];
    const float* lnfb  = (const float*)d_in[16];

    float *px, *ph, *pao, *pfc1, *pqkv;
    float *pwteT, *pqkvT, *pprojT, *pfc1T, *pfc2T;
    cudaGetSymbolAddress((void**)&px,    g_x);
    cudaGetSymbolAddress((void**)&ph,    g_h);
    cudaGetSymbolAddress((void**)&pao,   g_ao);
    cudaGetSymbolAddress((void**)&pfc1,  g_fc1);
    cudaGetSymbolAddress((void**)&pqkv,  g_qkv);
    cudaGetSymbolAddress((void**)&pwteT, g_wteT);
    cudaGetSymbolAddress((void**)&pqkvT, g_qkvT);
    cudaGetSymbolAddress((void**)&pprojT,g_projT);
    cudaGetSymbolAddress((void**)&pfc1T, g_fc1T);
    cudaGetSymbolAddress((void**)&pfc2T, g_fc2T);

    cudaFuncSetAttribute(tc_gemm_k<0>, cudaFuncAttributeMaxDynamicSharedMemorySize, SMEM_GEMM);
    cudaFuncSetAttribute(tc_gemm_k<1>, cudaFuncAttributeMaxDynamicSharedMemorySize, SMEM_GEMM);
    cudaFuncSetAttribute(tc_gemm_k<2>, cudaFuncAttributeMaxDynamicSharedMemorySize, SMEM_GEMM);
    cudaFuncSetAttribute(tc_gemm_k<3>, cudaFuncAttributeMaxDynamicSharedMemorySize, SMEM_GEMM);
    cudaFuncSetAttribute(flash_attn_k, cudaFuncAttributeMaxDynamicSharedMemorySize, FLASH_SMEM);

    // ---- weight prep (every replay; deterministic) ----
    wte_cvt_k<<<(int)(((size_t)NVP * ND + 255) / 256), 256>>>(wte);
    transpose_cvt_k<<<dim3(N3D / 32, ND / 32, NL), 256>>>(
        qkvw, pqkvT, ND, N3D, (size_t)ND * N3D, (size_t)N3D * ND);
    transpose_cvt_k<<<dim3(ND / 32, ND / 32, NL), 256>>>(
        projw, pprojT, ND, ND, (size_t)ND * ND, (size_t)ND * ND);
    transpose_cvt_k<<<dim3(N4D / 32, ND / 32, NL), 256>>>(
        fc1w, pfc1T, ND, N4D, (size_t)ND * N4D, (size_t)N4D * ND);
    transpose_cvt_k<<<dim3(ND / 32, N4D / 32, NL), 256>>>(
        fc2w, pfc2T, N4D, ND, (size_t)N4D * ND, (size_t)ND * N4D);

    embed_k<<<(NTOK * ND + 255) / 256, 256>>>(idx, wte, pos);

    for (int l = 0; l < NL; l++) {
        // --- attention half ---
        ln_k<<<NTOK, 256>>>(px, ln1g + (size_t)l * ND, ln1b + (size_t)l * ND, ph);

        tc_gemm_k<0><<<dim3(N3D / 128, NTOK / 128), 256, SMEM_GEMM>>>(
            ph, pqkvT + (size_t)l * N3D * ND, qkvb + (size_t)l * N3D,
            nullptr, pqkv, N3D, ND);

        flash_attn_k<<<dim3(NT / 64, NB * NH), 128, FLASH_SMEM>>>();

        tc_gemm_k<1><<<dim3(ND / 128, NTOK / 128), 256, SMEM_GEMM>>>(
            pao, pprojT + (size_t)l * ND * ND, projb + (size_t)l * ND,
            px, px, ND, ND);

        // --- MLP half ---
        ln_k<<<NTOK, 256>>>(px, ln2g + (size_t)l * ND, ln2b + (size_t)l * ND, ph);

        tc_gemm_k<2><<<dim3(N4D / 128, NTOK / 128), 256, SMEM_GEMM>>>(
            ph, pfc1T + (size_t)l * N4D * ND, fc1b + (size_t)l * N4D,
            nullptr, pfc1, N4D, ND);

        tc_gemm_k<1><<<dim3(ND / 128, NTOK / 128), 256, SMEM_GEMM>>>(
            pfc1, pfc2T + (size_t)l * ND * N4D, fc2b + (size_t)l * ND,
            px, px, ND, N4D);
    }

    // final LN + tied head
    ln_k<<<NTOK, 256>>>(px, lnfg, lnfb, ph);
    tc_gemm_k<3><<<dim3(NVP / 128, NTOK / 128), 256, SMEM_GEMM>>>(
        ph, pwteT, nullptr, nullptr, (float*)d_out, NV, ND);
}